// round 5
// baseline (speedup 1.0000x reference)
#include <cuda_runtime.h>
#include <cstdint>

#define NPTS 2048
#define BATCH 8
#define KNN 20
#define NEGINF __int_as_float(0xff800000)

// ---------------- static device scratch (no allocation allowed) ----------------
__device__ float d_S[(size_t)BATCH * NPTS * NPTS];   // 134 MB score matrix
__device__ int   d_idx[BATCH * NPTS * KNN];
__device__ float d_xx[BATCH * NPTS];
__device__ float d_x1[BATCH * NPTS * 64];
__device__ float d_x2[BATCH * NPTS * 64];
__device__ float d_x3[BATCH * NPTS * 128];
__device__ float d_x4[BATCH * NPTS * 256];
__device__ float d_W1t[6 * 64];
__device__ float d_W2t[128 * 64];
__device__ float d_W3t[128 * 128];
__device__ float d_W4t[256 * 256];
__device__ float d_W5t[512 * 512];
__device__ float d_h5[BATCH * 512];

// ---------------- small helpers ----------------
__device__ __forceinline__ void atomicMaxFloat(float* addr, float v) {
    if (v >= 0.f) atomicMax((int*)addr, __float_as_int(v));
    else          atomicMin((unsigned int*)addr, __float_as_uint(v));
}

// ---------------- weight transpose: Wt[c][o] = W[o][c] ----------------
__global__ void transpose_kernel(const float* __restrict__ W, float* __restrict__ Wt,
                                 int O, int Cin) {
    int i = blockIdx.x * 256 + threadIdx.x;
    if (i < O * Cin) {
        int o = i / Cin;
        int c = i - o * Cin;
        Wt[c * O + o] = W[i];
    }
}

// ---------------- squared norms: one warp per point ----------------
__global__ void norms_kernel(const float* __restrict__ X, int C) {
    int p = blockIdx.x * 4 + (threadIdx.x >> 5);
    int lane = threadIdx.x & 31;
    const float* row = X + (size_t)p * C;
    float s = 0.f;
    for (int c = lane; c < C; c += 32) { float v = row[c]; s += v * v; }
    #pragma unroll
    for (int off = 16; off; off >>= 1) s += __shfl_down_sync(0xffffffffu, s, off);
    if (lane == 0) d_xx[p] = s;
}

// ---------------- neg squared distance: 64x64 tiles, 4x4 microtiles ----------------
// Channel-major smem tiles: An[c][row] so the micro-tile reads are LDS.128,
// conflict-free / broadcast. Epilogue stores are float4 (STG.128).
template <int C>
__global__ void dist_kernel(const float* __restrict__ X) {
    int b = blockIdx.z;
    int n0 = blockIdx.y * 64, m0 = blockIdx.x * 64;
    __shared__ float An[16][68];
    __shared__ float Am[16][68];
    int tid = threadIdx.x;
    int jj = tid & 15, rr = tid >> 4;     // loader: channel jj, rows rr*4..rr*4+3
    int ty = tid >> 4, tx = tid & 15;     // compute: 4x4 tile at (ty*4, tx*4)
    float acc[4][4] = {};
    const float* Xb = X + (size_t)b * NPTS * C;

    for (int c0 = 0; c0 < C; c0 += 16) {
        int c = c0 + jj;
        bool cv = (c < C);
        #pragma unroll
        for (int q = 0; q < 4; q++) {
            int r = rr * 4 + q;
            An[jj][r] = cv ? Xb[(size_t)(n0 + r) * C + c] : 0.f;
            Am[jj][r] = cv ? Xb[(size_t)(m0 + r) * C + c] : 0.f;
        }
        __syncthreads();
        #pragma unroll
        for (int cc = 0; cc < 16; cc++) {
            float4 a4 = *(const float4*)&An[cc][ty * 4];
            float4 b4 = *(const float4*)&Am[cc][tx * 4];
            float a[4] = {a4.x, a4.y, a4.z, a4.w};
            float bb[4] = {b4.x, b4.y, b4.z, b4.w};
            #pragma unroll
            for (int i = 0; i < 4; i++)
                #pragma unroll
                for (int j = 0; j < 4; j++)
                    acc[i][j] += a[i] * bb[j];
        }
        __syncthreads();
    }

    float xm[4];
    #pragma unroll
    for (int j = 0; j < 4; j++) xm[j] = d_xx[b * NPTS + m0 + tx * 4 + j];
    #pragma unroll
    for (int i = 0; i < 4; i++) {
        int n = n0 + ty * 4 + i;
        float xn = d_xx[b * NPTS + n];
        float4 outv;
        outv.x = 2.f * acc[i][0] - xn - xm[0];
        outv.y = 2.f * acc[i][1] - xn - xm[1];
        outv.z = 2.f * acc[i][2] - xn - xm[2];
        outv.w = 2.f * acc[i][3] - xn - xm[3];
        *(float4*)&d_S[((size_t)b * NPTS + n) * NPTS + m0 + tx * 4] = outv;
    }
}

// ---------------- top-K per row: one warp per row, 20 argmax sweeps ----------------
__global__ void topk_kernel() {
    __shared__ float buf[4][NPTS];
    int w = threadIdx.x >> 5, lane = threadIdx.x & 31;
    int row = blockIdx.x * 4 + w;                // global row = b*NPTS + n
    const float* S = d_S + (size_t)row * NPTS;
    for (int m = lane; m < NPTS; m += 32) buf[w][m] = S[m];
    __syncwarp();
    for (int it = 0; it < KNN; it++) {
        float v = NEGINF; int mi = NPTS;
        for (int m = lane; m < NPTS; m += 32) {
            float x = buf[w][m];
            if (x > v) { v = x; mi = m; }       // first (smallest m) max kept
        }
        #pragma unroll
        for (int off = 16; off; off >>= 1) {
            float ov = __shfl_down_sync(0xffffffffu, v, off);
            int   oi = __shfl_down_sync(0xffffffffu, mi, off);
            if (ov > v || (ov == v && oi < mi)) { v = ov; mi = oi; }
        }
        mi = __shfl_sync(0xffffffffu, mi, 0);
        if (lane == 0) { d_idx[row * KNN + it] = mi; buf[w][mi] = NEGINF; }
        __syncwarp();
    }
}

// ---------------- edge conv: block per point, thread per output channel ----------------
template <int C, int O>
__global__ void edge_kernel(const float* __restrict__ X, const float* __restrict__ Wt,
                            const float* __restrict__ g, const float* __restrict__ bias,
                            float* __restrict__ Y) {
    int p = blockIdx.x;                 // b*NPTS + n
    int o = threadIdx.x;
    int b = p >> 11;                    // NPTS = 2048
    __shared__ float xn[C];
    __shared__ float diff[KNN * C];
    __shared__ int nbr[KNN];
    if (o < KNN) nbr[o] = d_idx[p * KNN + o];
    for (int c = o; c < C; c += O) xn[c] = X[(size_t)p * C + c];
    __syncthreads();
    for (int e = o; e < KNN * C; e += O) {
        int k = e / C, c = e - k * C;
        diff[e] = X[(size_t)(b * NPTS + nbr[k]) * C + c] - xn[c];
    }
    __syncthreads();

    float scale = g[o] * rsqrtf(1.f + 1e-5f);
    float bb = bias[o];

    float center = 0.f;
    #pragma unroll 4
    for (int c = 0; c < C; c++) center += xn[c] * Wt[(C + c) * O + o];

    float acc[KNN];
    #pragma unroll
    for (int k = 0; k < KNN; k++) acc[k] = center;

    for (int c = 0; c < C; c++) {
        float w = Wt[c * O + o];
        #pragma unroll
        for (int k = 0; k < KNN; k++) acc[k] += diff[k * C + c] * w;
    }

    float m = NEGINF;
    #pragma unroll
    for (int k = 0; k < KNN; k++) {
        float h = acc[k] * scale + bb;
        h = (h >= 0.f) ? h : 0.2f * h;
        m = fmaxf(m, h);
    }
    Y[(size_t)p * O + o] = m;
}

// ---------------- init h5 to -inf ----------------
__global__ void init_h5() {
    d_h5[blockIdx.x * blockDim.x + threadIdx.x] = NEGINF;
}

// ---------------- concat + W5 + bn/lrelu + max over N (per batch) ----------------
__global__ void fuse_kernel(const float* __restrict__ g5, const float* __restrict__ b5) {
    int b = blockIdx.y;
    int n0 = blockIdx.x * 16;
    int t = threadIdx.x;                 // 256 threads
    __shared__ float xc[16][512];
    for (int e = t; e < 16 * 512; e += 256) {
        int pp = e >> 9, c = e & 511;
        int p = b * NPTS + n0 + pp;
        float v;
        if      (c < 64)  v = d_x1[(size_t)p * 64  + c];
        else if (c < 128) v = d_x2[(size_t)p * 64  + (c - 64)];
        else if (c < 256) v = d_x3[(size_t)p * 128 + (c - 128)];
        else              v = d_x4[(size_t)p * 256 + (c - 256)];
        xc[pp][c] = v;
    }
    __syncthreads();

    float a0[16] = {}, a1[16] = {};
    int o0 = t, o1 = t + 256;
    for (int c = 0; c < 512; c++) {
        float w0 = d_W5t[c * 512 + o0];
        float w1 = d_W5t[c * 512 + o1];
        #pragma unroll
        for (int pp = 0; pp < 16; pp++) {
            float xv = xc[pp][c];
            a0[pp] += xv * w0;
            a1[pp] += xv * w1;
        }
    }
    float s0 = g5[o0] * rsqrtf(1.f + 1e-5f), s1 = g5[o1] * rsqrtf(1.f + 1e-5f);
    float c0 = b5[o0], c1 = b5[o1];
    float m0 = NEGINF, m1 = NEGINF;
    #pragma unroll
    for (int pp = 0; pp < 16; pp++) {
        float h0 = a0[pp] * s0 + c0; h0 = (h0 >= 0.f) ? h0 : 0.2f * h0; m0 = fmaxf(m0, h0);
        float h1 = a1[pp] * s1 + c1; h1 = (h1 >= 0.f) ? h1 : 0.2f * h1; m1 = fmaxf(m1, h1);
    }
    atomicMaxFloat(&d_h5[b * 512 + o0], m0);
    atomicMaxFloat(&d_h5[b * 512 + o1], m1);
}

// ---------------- final: feat copy + embedding GEMV ----------------
__global__ void final_kernel(const float* __restrict__ Wemb, float* __restrict__ out) {
    int b = blockIdx.x;
    int t = threadIdx.x;                 // 512 threads
    __shared__ float h[512];
    float v = d_h5[b * 512 + t];
    h[t] = v;
    out[b * 512 + t] = v;                // feat (8,1,512)
    __syncthreads();
    if (t < 256) {
        float s = 0.f;
        #pragma unroll 4
        for (int c = 0; c < 512; c++) s += h[c] * Wemb[t * 512 + c];
        out[BATCH * 512 + b * 256 + t] = s;   // embedding (8,256)
    }
}

// ---------------- launch ----------------
extern "C" void kernel_launch(void* const* d_in, const int* in_sizes, int n_in,
                              void* d_out, int out_size) {
    const float* x    = (const float*)d_in[0];
    const float* W1   = (const float*)d_in[1];
    const float* g1   = (const float*)d_in[2];
    const float* b1   = (const float*)d_in[3];
    const float* W2   = (const float*)d_in[4];
    const float* g2   = (const float*)d_in[5];
    const float* b2   = (const float*)d_in[6];
    const float* W3   = (const float*)d_in[7];
    const float* g3   = (const float*)d_in[8];
    const float* b3   = (const float*)d_in[9];
    const float* W4   = (const float*)d_in[10];
    const float* g4   = (const float*)d_in[11];
    const float* b4   = (const float*)d_in[12];
    const float* W5   = (const float*)d_in[13];
    const float* g5   = (const float*)d_in[14];
    const float* b5   = (const float*)d_in[15];
    const float* Wemb = (const float*)d_in[16];
    float* out = (float*)d_out;

    float *pW1t, *pW2t, *pW3t, *pW4t, *pW5t, *px1, *px2, *px3, *px4;
    cudaGetSymbolAddress((void**)&pW1t, d_W1t);
    cudaGetSymbolAddress((void**)&pW2t, d_W2t);
    cudaGetSymbolAddress((void**)&pW3t, d_W3t);
    cudaGetSymbolAddress((void**)&pW4t, d_W4t);
    cudaGetSymbolAddress((void**)&pW5t, d_W5t);
    cudaGetSymbolAddress((void**)&px1, d_x1);
    cudaGetSymbolAddress((void**)&px2, d_x2);
    cudaGetSymbolAddress((void**)&px3, d_x3);
    cudaGetSymbolAddress((void**)&px4, d_x4);

    transpose_kernel<<<(64 * 6 + 255) / 256, 256>>>(W1, pW1t, 64, 6);
    transpose_kernel<<<(64 * 128 + 255) / 256, 256>>>(W2, pW2t, 64, 128);
    transpose_kernel<<<(128 * 128 + 255) / 256, 256>>>(W3, pW3t, 128, 128);
    transpose_kernel<<<(256 * 256 + 255) / 256, 256>>>(W4, pW4t, 256, 256);
    transpose_kernel<<<(512 * 512 + 255) / 256, 256>>>(W5, pW5t, 512, 512);

    dim3 dg(NPTS / 64, NPTS / 64, BATCH);
    int nrows = BATCH * NPTS;            // 16384

    // Layer 1: C=3 -> O=64
    norms_kernel<<<nrows / 4, 128>>>(x, 3);
    dist_kernel<3><<<dg, 256>>>(x);
    topk_kernel<<<nrows / 4, 128>>>();
    edge_kernel<3, 64><<<nrows, 64>>>(x, pW1t, g1, b1, px1);

    // Layer 2: C=64 -> O=64
    norms_kernel<<<nrows / 4, 128>>>(px1, 64);
    dist_kernel<64><<<dg, 256>>>(px1);
    topk_kernel<<<nrows / 4, 128>>>();
    edge_kernel<64, 64><<<nrows, 64>>>(px1, pW2t, g2, b2, px2);

    // Layer 3: C=64 -> O=128
    norms_kernel<<<nrows / 4, 128>>>(px2, 64);
    dist_kernel<64><<<dg, 256>>>(px2);
    topk_kernel<<<nrows / 4, 128>>>();
    edge_kernel<64, 128><<<nrows, 128>>>(px2, pW3t, g3, b3, px3);

    // Layer 4: C=128 -> O=256
    norms_kernel<<<nrows / 4, 128>>>(px3, 128);
    dist_kernel<128><<<dg, 256>>>(px3);
    topk_kernel<<<nrows / 4, 128>>>();
    edge_kernel<128, 256><<<nrows, 256>>>(px3, pW4t, g4, b4, px4);

    // Final fuse + reductions
    init_h5<<<8, 512>>>();
    fuse_kernel<<<dim3(NPTS / 16, BATCH), 256>>>(g5, b5);
    final_kernel<<<BATCH, 512>>>(Wemb, out);
}

// round 7
// speedup vs baseline: 1.1780x; 1.1780x over previous
#include <cuda_runtime.h>
#include <cstdint>

#define NPTS 2048
#define BATCH 8
#define KNN 20
#define NEGINF __int_as_float(0xff800000)

typedef unsigned long long u64;

// ---------------- static device scratch (no allocation allowed) ----------------
__device__ float d_S[(size_t)BATCH * NPTS * NPTS];   // 134 MB score matrix
__device__ int   d_idx[BATCH * NPTS * KNN];
__device__ float d_xx[BATCH * NPTS];
__device__ float d_x1[BATCH * NPTS * 64];
__device__ float d_x2[BATCH * NPTS * 64];
__device__ float d_x3[BATCH * NPTS * 128];
__device__ float d_x4[BATCH * NPTS * 256];
// packed edge-conv weights: diff part and center part, u64 = {W[o][2c], W[o][2c+1]}
__device__ u64  d_Wp1d[2 * 64],    d_Wp1c[2 * 64];      // C=3 -> Cp=4
__device__ u64  d_Wp2d[32 * 64],   d_Wp2c[32 * 64];     // C=64
__device__ u64  d_Wp3d[32 * 128],  d_Wp3c[32 * 128];    // C=64
__device__ u64  d_Wp4d[64 * 256],  d_Wp4c[64 * 256];    // C=128
__device__ float d_W5t[512 * 512];
__device__ float d_h5[BATCH * 512];

// ---------------- f32x2 helpers ----------------
__device__ __forceinline__ u64 fma2(u64 a, u64 b, u64 c) {
    u64 d;
    asm("fma.rn.f32x2 %0, %1, %2, %3;" : "=l"(d) : "l"(a), "l"(b), "l"(c));
    return d;
}
__device__ __forceinline__ u64 pack2(float lo, float hi) {
    u64 d;
    asm("mov.b64 %0, {%1, %2};" : "=l"(d) : "f"(lo), "f"(hi));
    return d;
}
__device__ __forceinline__ float2 unpack2(u64 v) {
    float2 r;
    asm("mov.b64 {%0, %1}, %2;" : "=f"(r.x), "=f"(r.y) : "l"(v));
    return r;
}

__device__ __forceinline__ void atomicMaxFloat(float* addr, float v) {
    if (v >= 0.f) atomicMax((int*)addr, __float_as_int(v));
    else          atomicMin((unsigned int*)addr, __float_as_uint(v));
}

// ---------------- pack edge-conv weights: W is (O, 2C) row-major ----------------
__global__ void pack_kernel(const float* __restrict__ W, u64* __restrict__ Wpd,
                            u64* __restrict__ Wpc, int O, int C, int Cp) {
    int i = blockIdx.x * 256 + threadIdx.x;
    int total = (Cp / 2) * O;
    if (i >= total) return;
    int c2 = i / O, o = i - c2 * O;
    int c0 = 2 * c2, c1 = 2 * c2 + 1;
    const float* row = W + (size_t)o * 2 * C;
    float a0 = (c0 < C) ? row[c0] : 0.f;
    float a1 = (c1 < C) ? row[c1] : 0.f;
    Wpd[c2 * O + o] = pack2(a0, a1);
    float e0 = (c0 < C) ? row[C + c0] : 0.f;
    float e1 = (c1 < C) ? row[C + c1] : 0.f;
    Wpc[c2 * O + o] = pack2(e0, e1);
}

// ---------------- weight transpose for W5: Wt[c][o] = W[o][c] ----------------
__global__ void transpose_kernel(const float* __restrict__ W, float* __restrict__ Wt,
                                 int O, int Cin) {
    int i = blockIdx.x * 256 + threadIdx.x;
    if (i < O * Cin) {
        int o = i / Cin;
        int c = i - o * Cin;
        Wt[c * O + o] = W[i];
    }
}

// ---------------- squared norms: one warp per point ----------------
__global__ void norms_kernel(const float* __restrict__ X, int C) {
    int p = blockIdx.x * 4 + (threadIdx.x >> 5);
    int lane = threadIdx.x & 31;
    const float* row = X + (size_t)p * C;
    float s = 0.f;
    for (int c = lane; c < C; c += 32) { float v = row[c]; s += v * v; }
    #pragma unroll
    for (int off = 16; off; off >>= 1) s += __shfl_down_sync(0xffffffffu, s, off);
    if (lane == 0) d_xx[p] = s;
}

// ---------------- neg squared distance: 64x64 tiles, 4x4 microtiles, f32x2 ----------------
template <int C>
__global__ void dist_kernel(const float* __restrict__ X) {
    int b = blockIdx.z;
    int n0 = blockIdx.y * 64, m0 = blockIdx.x * 64;
    __shared__ __align__(16) float An[16][68];
    __shared__ __align__(16) float Am[16][68];
    int tid = threadIdx.x;
    int jj = tid & 15, rr = tid >> 4;     // loader: channel jj, rows rr*4..rr*4+3
    int ty = tid >> 4, tx = tid & 15;     // compute: 4x4 tile at (ty*4, tx*4)
    u64 acc2[4][2];
    #pragma unroll
    for (int i = 0; i < 4; i++) { acc2[i][0] = 0ull; acc2[i][1] = 0ull; }
    const float* Xb = X + (size_t)b * NPTS * C;

    for (int c0 = 0; c0 < C; c0 += 16) {
        int c = c0 + jj;
        bool cv = (c < C);
        #pragma unroll
        for (int q = 0; q < 4; q++) {
            int r = rr * 4 + q;
            An[jj][r] = cv ? Xb[(size_t)(n0 + r) * C + c] : 0.f;
            Am[jj][r] = cv ? Xb[(size_t)(m0 + r) * C + c] : 0.f;
        }
        __syncthreads();
        #pragma unroll
        for (int cc = 0; cc < 16; cc++) {
            float4 a4 = *(const float4*)&An[cc][ty * 4];
            ulonglong2 b2 = *(const ulonglong2*)&Am[cc][tx * 4];
            u64 ad;
            ad = pack2(a4.x, a4.x);
            acc2[0][0] = fma2(ad, b2.x, acc2[0][0]);
            acc2[0][1] = fma2(ad, b2.y, acc2[0][1]);
            ad = pack2(a4.y, a4.y);
            acc2[1][0] = fma2(ad, b2.x, acc2[1][0]);
            acc2[1][1] = fma2(ad, b2.y, acc2[1][1]);
            ad = pack2(a4.z, a4.z);
            acc2[2][0] = fma2(ad, b2.x, acc2[2][0]);
            acc2[2][1] = fma2(ad, b2.y, acc2[2][1]);
            ad = pack2(a4.w, a4.w);
            acc2[3][0] = fma2(ad, b2.x, acc2[3][0]);
            acc2[3][1] = fma2(ad, b2.y, acc2[3][1]);
        }
        __syncthreads();
    }

    float xm[4];
    #pragma unroll
    for (int j = 0; j < 4; j++) xm[j] = d_xx[b * NPTS + m0 + tx * 4 + j];
    #pragma unroll
    for (int i = 0; i < 4; i++) {
        int n = n0 + ty * 4 + i;
        float xn = d_xx[b * NPTS + n];
        float2 p01 = unpack2(acc2[i][0]);
        float2 p23 = unpack2(acc2[i][1]);
        float4 outv;
        outv.x = 2.f * p01.x - xn - xm[0];
        outv.y = 2.f * p01.y - xn - xm[1];
        outv.z = 2.f * p23.x - xn - xm[2];
        outv.w = 2.f * p23.y - xn - xm[3];
        *(float4*)&d_S[((size_t)b * NPTS + n) * NPTS + m0 + tx * 4] = outv;
    }
}

// ---------------- top-K per row: one warp per row, 20 argmax sweeps ----------------
__global__ void topk_kernel() {
    __shared__ float buf[4][NPTS];
    int w = threadIdx.x >> 5, lane = threadIdx.x & 31;
    int row = blockIdx.x * 4 + w;                // global row = b*NPTS + n
    const float* S = d_S + (size_t)row * NPTS;
    for (int m = lane; m < NPTS; m += 32) buf[w][m] = S[m];
    __syncwarp();
    for (int it = 0; it < KNN; it++) {
        float v = NEGINF; int mi = NPTS;
        for (int m = lane; m < NPTS; m += 32) {
            float x = buf[w][m];
            if (x > v) { v = x; mi = m; }       // first (smallest m) max kept
        }
        #pragma unroll
        for (int off = 16; off; off >>= 1) {
            float ov = __shfl_down_sync(0xffffffffu, v, off);
            int   oi = __shfl_down_sync(0xffffffffu, mi, off);
            if (ov > v || (ov == v && oi < mi)) { v = ov; mi = oi; }
        }
        mi = __shfl_sync(0xffffffffu, mi, 0);
        if (lane == 0) { d_idx[row * KNN + it] = mi; buf[w][mi] = NEGINF; }
        __syncwarp();
    }
}

// ---------------- edge conv: block per point, thread per output channel, f32x2 ----------------
// Cp = C rounded up to power-of-2 multiple of 4 (4, 64, 128)
template <int C, int Cp, int O>
__global__ void edge_kernel(const float* __restrict__ X,
                            const u64* __restrict__ Wpd, const u64* __restrict__ Wpc,
                            const float* __restrict__ g, const float* __restrict__ bias,
                            float* __restrict__ Y) {
    int p = blockIdx.x;                 // b*NPTS + n
    int o = threadIdx.x;
    int b = p >> 11;                    // NPTS = 2048
    __shared__ __align__(16) float xn[Cp];
    __shared__ __align__(16) float diff[KNN * Cp];
    __shared__ int nbr[KNN];
    if (o < KNN) nbr[o] = d_idx[p * KNN + o];
    for (int c = o; c < Cp; c += O) xn[c] = (c < C) ? X[(size_t)p * C + c] : 0.f;
    __syncthreads();
    const float* Xb = X + (size_t)b * NPTS * C;
    for (int e = o; e < KNN * Cp; e += O) {
        int k = e / Cp, c = e - k * Cp;
        diff[e] = (c < C) ? Xb[(size_t)nbr[k] * C + c] - xn[c] : 0.f;
    }
    __syncthreads();

    // center term: sum_c xn[c] * Wcen[c][o]  (packed pairs)
    u64 cen2 = 0ull;
    #pragma unroll 4
    for (int c2 = 0; c2 < Cp / 2; c2++) {
        u64 x2 = *(const u64*)&xn[2 * c2];
        cen2 = fma2(x2, Wpc[c2 * O + o], cen2);
    }
    float2 cf = unpack2(cen2);
    float center = cf.x + cf.y;

    u64 acc2[KNN];
    #pragma unroll
    for (int k = 0; k < KNN; k++) acc2[k] = 0ull;

    #pragma unroll 2
    for (int c4 = 0; c4 < Cp / 4; c4++) {
        u64 wa = Wpd[(2 * c4) * O + o];
        u64 wb = Wpd[(2 * c4 + 1) * O + o];
        #pragma unroll
        for (int k = 0; k < KNN; k++) {
            ulonglong2 dv = *(const ulonglong2*)&diff[k * Cp + 4 * c4];
            acc2[k] = fma2(dv.x, wa, acc2[k]);
            acc2[k] = fma2(dv.y, wb, acc2[k]);
        }
    }

    float scale = g[o] * rsqrtf(1.f + 1e-5f);
    float bb = bias[o];
    float m = NEGINF;
    #pragma unroll
    for (int k = 0; k < KNN; k++) {
        float2 t = unpack2(acc2[k]);
        float h = (t.x + t.y + center) * scale + bb;
        h = (h >= 0.f) ? h : 0.2f * h;
        m = fmaxf(m, h);
    }
    Y[(size_t)p * O + o] = m;
}

// ---------------- init h5 to -inf ----------------
__global__ void init_h5() {
    d_h5[blockIdx.x * blockDim.x + threadIdx.x] = NEGINF;
}

// ---------------- concat + W5 + bn/lrelu + max over N (per batch), f32x2 ----------------
__global__ void fuse_kernel(const float* __restrict__ g5, const float* __restrict__ b5) {
    int b = blockIdx.y;
    int n0 = blockIdx.x * 16;
    int t = threadIdx.x;                 // 256 threads
    __shared__ __align__(16) float xc[512][18];   // [channel][point], padded stride
    for (int e = t; e < 16 * 512; e += 256) {
        int pp = e >> 9, c = e & 511;
        int p = b * NPTS + n0 + pp;
        float v;
        if      (c < 64)  v = d_x1[(size_t)p * 64  + c];
        else if (c < 128) v = d_x2[(size_t)p * 64  + (c - 64)];
        else if (c < 256) v = d_x3[(size_t)p * 128 + (c - 128)];
        else              v = d_x4[(size_t)p * 256 + (c - 256)];
        xc[c][pp] = v;
    }
    __syncthreads();

    u64 a0[8], a1[8];
    #pragma unroll
    for (int q = 0; q < 8; q++) { a0[q] = 0ull; a1[q] = 0ull; }
    int o0 = t, o1 = t + 256;
    #pragma unroll 2
    for (int c = 0; c < 512; c++) {
        float w0 = d_W5t[c * 512 + o0];
        float w1 = d_W5t[c * 512 + o1];
        u64 w02 = pack2(w0, w0);
        u64 w12 = pack2(w1, w1);
        #pragma unroll
        for (int q = 0; q < 8; q++) {
            u64 xv = *(const u64*)&xc[c][2 * q];
            a0[q] = fma2(xv, w02, a0[q]);
            a1[q] = fma2(xv, w12, a1[q]);
        }
    }
    float s0 = g5[o0] * rsqrtf(1.f + 1e-5f), s1 = g5[o1] * rsqrtf(1.f + 1e-5f);
    float c0 = b5[o0], c1 = b5[o1];
    float m0 = NEGINF, m1 = NEGINF;
    #pragma unroll
    for (int q = 0; q < 8; q++) {
        float2 v0 = unpack2(a0[q]);
        float2 v1 = unpack2(a1[q]);
        float h;
        h = v0.x * s0 + c0; h = (h >= 0.f) ? h : 0.2f * h; m0 = fmaxf(m0, h);
        h = v0.y * s0 + c0; h = (h >= 0.f) ? h : 0.2f * h; m0 = fmaxf(m0, h);
        h = v1.x * s1 + c1; h = (h >= 0.f) ? h : 0.2f * h; m1 = fmaxf(m1, h);
        h = v1.y * s1 + c1; h = (h >= 0.f) ? h : 0.2f * h; m1 = fmaxf(m1, h);
    }
    atomicMaxFloat(&d_h5[b * 512 + o0], m0);
    atomicMaxFloat(&d_h5[b * 512 + o1], m1);
}

// ---------------- final: feat copy + embedding GEMV ----------------
__global__ void final_kernel(const float* __restrict__ Wemb, float* __restrict__ out) {
    int b = blockIdx.x;
    int t = threadIdx.x;                 // 512 threads
    __shared__ float h[512];
    float v = d_h5[b * 512 + t];
    h[t] = v;
    out[b * 512 + t] = v;                // feat (8,1,512)
    __syncthreads();
    if (t < 256) {
        float s = 0.f;
        #pragma unroll 4
        for (int c = 0; c < 512; c++) s += h[c] * Wemb[t * 512 + c];
        out[BATCH * 512 + b * 256 + t] = s;   // embedding (8,256)
    }
}

// ---------------- launch ----------------
extern "C" void kernel_launch(void* const* d_in, const int* in_sizes, int n_in,
                              void* d_out, int out_size) {
    const float* x    = (const float*)d_in[0];
    const float* W1   = (const float*)d_in[1];
    const float* g1   = (const float*)d_in[2];
    const float* b1   = (const float*)d_in[3];
    const float* W2   = (const float*)d_in[4];
    const float* g2   = (const float*)d_in[5];
    const float* b2   = (const float*)d_in[6];
    const float* W3   = (const float*)d_in[7];
    const float* g3   = (const float*)d_in[8];
    const float* b3   = (const float*)d_in[9];
    const float* W4   = (const float*)d_in[10];
    const float* g4   = (const float*)d_in[11];
    const float* b4   = (const float*)d_in[12];
    const float* W5   = (const float*)d_in[13];
    const float* g5   = (const float*)d_in[14];
    const float* b5   = (const float*)d_in[15];
    const float* Wemb = (const float*)d_in[16];
    float* out = (float*)d_out;

    float *pW5t, *px1, *px2, *px3, *px4;
    u64 *pWp1d, *pWp1c, *pWp2d, *pWp2c, *pWp3d, *pWp3c, *pWp4d, *pWp4c;
    cudaGetSymbolAddress((void**)&pW5t, d_W5t);
    cudaGetSymbolAddress((void**)&px1, d_x1);
    cudaGetSymbolAddress((void**)&px2, d_x2);
    cudaGetSymbolAddress((void**)&px3, d_x3);
    cudaGetSymbolAddress((void**)&px4, d_x4);
    cudaGetSymbolAddress((void**)&pWp1d, d_Wp1d);
    cudaGetSymbolAddress((void**)&pWp1c, d_Wp1c);
    cudaGetSymbolAddress((void**)&pWp2d, d_Wp2d);
    cudaGetSymbolAddress((void**)&pWp2c, d_Wp2c);
    cudaGetSymbolAddress((void**)&pWp3d, d_Wp3d);
    cudaGetSymbolAddress((void**)&pWp3c, d_Wp3c);
    cudaGetSymbolAddress((void**)&pWp4d, d_Wp4d);
    cudaGetSymbolAddress((void**)&pWp4c, d_Wp4c);

    pack_kernel<<<1, 256>>>(W1, pWp1d, pWp1c, 64, 3, 4);
    pack_kernel<<<(32 * 64 + 255) / 256, 256>>>(W2, pWp2d, pWp2c, 64, 64, 64);
    pack_kernel<<<(32 * 128 + 255) / 256, 256>>>(W3, pWp3d, pWp3c, 128, 64, 64);
    pack_kernel<<<(64 * 256 + 255) / 256, 256>>>(W4, pWp4d, pWp4c, 256, 128, 128);
    transpose_kernel<<<(512 * 512 + 255) / 256, 256>>>(W5, pW5t, 512, 512);

    dim3 dg(NPTS / 64, NPTS / 64, BATCH);
    int nrows = BATCH * NPTS;            // 16384

    // Layer 1: C=3 -> O=64
    norms_kernel<<<nrows / 4, 128>>>(x, 3);
    dist_kernel<3><<<dg, 256>>>(x);
    topk_kernel<<<nrows / 4, 128>>>();
    edge_kernel<3, 4, 64><<<nrows, 64>>>(x, pWp1d, pWp1c, g1, b1, px1);

    // Layer 2: C=64 -> O=64
    norms_kernel<<<nrows / 4, 128>>>(px1, 64);
    dist_kernel<64><<<dg, 256>>>(px1);
    topk_kernel<<<nrows / 4, 128>>>();
    edge_kernel<64, 64, 64><<<nrows, 64>>>(px1, pWp2d, pWp2c, g2, b2, px2);

    // Layer 3: C=64 -> O=128
    norms_kernel<<<nrows / 4, 128>>>(px2, 64);
    dist_kernel<64><<<dg, 256>>>(px2);
    topk_kernel<<<nrows / 4, 128>>>();
    edge_kernel<64, 64, 128><<<nrows, 128>>>(px2, pWp3d, pWp3c, g3, b3, px3);

    // Layer 4: C=128 -> O=256
    norms_kernel<<<nrows / 4, 128>>>(px3, 128);
    dist_kernel<128><<<dg, 256>>>(px3);
    topk_kernel<<<nrows / 4, 128>>>();
    edge_kernel<128, 128, 256><<<nrows, 256>>>(px3, pWp4d, pWp4c, g4, b4, px4);

    // Final fuse + reductions
    init_h5<<<8, 512>>>();
    fuse_kernel<<<dim3(NPTS / 16, BATCH), 256>>>(g5, b5);
    final_kernel<<<BATCH, 512>>>(Wemb, out);
}